// round 14
// baseline (speedup 1.0000x reference)
#include <cuda_runtime.h>
#include <cstddef>

#define Tn 10
#define Bn 4
#define Cc 64
#define Hh 64
#define Ww 64
#define HWp 4096

// kA: 16x16 tile, 18-row halo, row stride 20
#define RS_A 20
#define ICS_A 360
#define SM_IN_A (64*ICS_A)          // 23040 floats
#define SW_A (8*32*12)              // 3072 floats: 8ic x 32oc x stride12
#define SMEM_A ((SM_IN_A + SW_A)*4) // 104448 B -> 2 blocks/SM

// kB: 16x8 tile, 10-row halo, row stride 20
#define RS_B 20
#define ICS_B 200
#define SM_IN_B (64*ICS_B)
#define SW_B 1536
#define SMEM_B ((SM_IN_B + SW_B)*4)    // 57344 B

__device__ float g_prev_y [Bn*Cc*HWp];
__device__ float g_h      [Bn*Cc*HWp];
__device__ float g_gate_in[Bn*Cc*HWp];
__device__ float g_upd    [Bn*Cc*HWp];
__device__ float g_thr    [Bn*HWp];

__device__ __forceinline__ float sigmoidf_(float x) { return 1.0f / (1.0f + __expf(-x)); }

// ---------------------------------------------------------------------------
// Kernel 0 (t=0 only): all state zero -> convs reduce to biases. Exact.
// ---------------------------------------------------------------------------
__global__ void __launch_bounds__(256)
k0(const float* __restrict__ xt, const float* __restrict__ b_rz,
   const float* __restrict__ b_f, float* __restrict__ out)
{
    const int i4  = blockIdx.x * 256 + threadIdx.x;
    const int idx = i4 * 4;
    const int b   = idx >> 18;
    const int c   = (idx >> 12) & 63;

    const float thr = sigmoidf_(b_rz[128]);
    const float bz  = b_rz[c];
    const float bf  = b_f[c];

    float4 xz = *(const float4*)&xt[((size_t)b * 192 + c) * HWp + (idx & 4095)];
    float4 xf = *(const float4*)&xt[((size_t)b * 192 + 128 + c) * HWp + (idx & 4095)];
    const float xzv[4] = {xz.x, xz.y, xz.z, xz.w};
    const float xfv[4] = {xf.x, xf.y, xf.z, xf.w};

    float4 yv, ev4, nd4, hn4;
    float* yp  = &yv.x;  float* evp = &ev4.x;
    float* ndp = &nd4.x; float* hnp = &hn4.x;

    #pragma unroll
    for (int p = 0; p < 4; p++) {
        float u   = sigmoidf_(bz + xzv[p]);
        float ig  = tanhf(bf + xfv[p]);
        float h   = u * ig;
        float d   = h - thr;
        float evt = (d > 0.0f) ? 1.0f : 0.0f;
        yp[p]  = evt * h;
        evp[p] = evt;
        ndp[p] = (d < 0.0f) ? (thr - h) : 0.0f;
        hnp[p] = h - evt * thr;
    }

    const size_t N = (size_t)Tn * Bn * Cc * HWp;
    *(float4*)&out[idx]          = yv;
    *(float4*)&out[N + idx]      = ev4;
    *(float4*)&out[2 * N + idx]  = nd4;
    *(float4*)&g_prev_y[idx]     = yv;
    *(float4*)&g_h[idx]          = hn4;
}

// ---------------------------------------------------------------------------
// Kernel A: 512 threads, 32 oc/block (4 oc x 4 consecutive px per thread),
// vectorized mac (kB-style), 16x16 tile. grid (16,4,4)=256 blocks.
// Target: 64 regs -> 2 blocks/SM -> 32 warps/SM. thr channel in grp 0.
// ---------------------------------------------------------------------------
__global__ void __launch_bounds__(512, 2)
kA(const float* __restrict__ xt, const float* __restrict__ w_rz,
   const float* __restrict__ b_rz, int t)
{
    extern __shared__ float smem[];
    float* s_in = smem;
    float* s_w  = smem + SM_IN_A;

    const int tid  = threadIdx.x;
    const int tile = blockIdx.x;   // 0..15
    const int grp  = blockIdx.y;   // 0..3
    const int b    = blockIdx.z;
    const int ty0  = (tile >> 2) * 16;
    const int tx0  = (tile & 3) * 16;

    for (int idx = tid; idx < 64 * 324; idx += 512) {
        int ic  = idx / 324;
        int rem = idx - ic * 324;
        int r   = rem / 18;
        int cc  = rem - r * 18;
        int gy  = ty0 + r - 1;
        int gx  = tx0 + cc - 1;
        float v = 0.0f;
        if (gy >= 0 && gy < Hh && gx >= 0 && gx < Ww)
            v = g_prev_y[((b * Cc + ic) * Hh + gy) * Ww + gx];
        s_in[ic * ICS_A + r * RS_A + cc] = v;
    }

    const int oc_base = grp * 32;
    const int ocq = tid >> 6;           // 0..7 (warp-uniform)
    const int pg  = tid & 63;
    const int py  = pg >> 2;            // 0..15
    const int xb  = (pg & 3) * 4;       // 0,4,8,12

    float acc[4][4];
    #pragma unroll
    for (int k = 0; k < 4; k++)
        #pragma unroll
        for (int p = 0; p < 4; p++) acc[k][p] = 0.0f;

    for (int cc0 = 0; cc0 < 64; cc0 += 8) {
        __syncthreads();
        // stage 8ic x 32oc x 9 -> s_w[icl][oc][12]
        for (int i = tid; i < 2304; i += 512) {
            int icl = i / 288;
            int rem = i - icl * 288;
            int oc  = rem / 9;
            int tap = rem - oc * 9;
            s_w[icl * 384 + oc * 12 + tap] =
                w_rz[(oc_base + oc) * 576 + (cc0 + icl) * 9 + tap];
        }
        __syncthreads();
        #pragma unroll
        for (int icl = 0; icl < 8; icl++) {
            const float* sin = s_in + (cc0 + icl) * ICS_A + py * RS_A + xb;
            float x[3][8];
            #pragma unroll
            for (int dy = 0; dy < 3; dy++) {
                float4 a  = *(const float4*)(sin + dy * RS_A);
                float4 b4 = *(const float4*)(sin + dy * RS_A + 4);
                x[dy][0]=a.x;  x[dy][1]=a.y;  x[dy][2]=a.z;  x[dy][3]=a.w;
                x[dy][4]=b4.x; x[dy][5]=b4.y; x[dy][6]=b4.z; x[dy][7]=b4.w;
            }
            const float* sw = s_w + icl * 384 + (ocq * 4) * 12;
            #pragma unroll
            for (int k = 0; k < 4; k++) {
                float4 w0 = *(const float4*)(sw + k * 12);
                float4 w1 = *(const float4*)(sw + k * 12 + 4);
                float  w8 = sw[k * 12 + 8];
                float wv[9] = {w0.x, w0.y, w0.z, w0.w, w1.x, w1.y, w1.z, w1.w, w8};
                #pragma unroll
                for (int dy = 0; dy < 3; dy++)
                    #pragma unroll
                    for (int dx = 0; dx < 3; dx++) {
                        float wt = wv[dy * 3 + dx];
                        #pragma unroll
                        for (int p = 0; p < 4; p++)
                            acc[k][p] += wt * x[dy][dx + p];
                    }
            }
        }
    }

    // Epilogue: gates (float4 stores; oc block is 32-aligned so grp<2 <=> z)
    const int gy   = ty0 + py;
    const int pix0 = gy * Ww + tx0 + xb;
    #pragma unroll
    for (int k = 0; k < 4; k++) {
        int oc = oc_base + ocq * 4 + k;
        float bias = b_rz[oc];
        float4 xi = *(const float4*)&xt[((((size_t)t * Bn + b) * 192) + oc) * HWp + pix0];
        float4 sg;
        sg.x = sigmoidf_(acc[k][0] + bias + xi.x);
        sg.y = sigmoidf_(acc[k][1] + bias + xi.y);
        sg.z = sigmoidf_(acc[k][2] + bias + xi.z);
        sg.w = sigmoidf_(acc[k][3] + bias + xi.w);
        if (grp < 2) {
            *(float4*)&g_upd[(size_t)(b * Cc + oc) * HWp + pix0] = sg;
        } else {
            int c = oc - 64;
            const float* sp = s_in + c * ICS_A + (py + 1) * RS_A + xb + 1;
            float4 g;
            g.x = sp[0] * sg.x; g.y = sp[1] * sg.y;
            g.z = sp[2] * sg.z; g.w = sp[3] * sg.w;
            *(float4*)&g_gate_in[(size_t)(b * Cc + c) * HWp + pix0] = g;
        }
    }

    // Threshold channel (oc 128): grp 0 blocks only; 256 px, tid<256
    if (grp == 0) {
        __syncthreads();
        for (int i = tid; i < 576; i += 512)
            s_w[i] = w_rz[128 * 576 + i];
        __syncthreads();
        if (tid < 256) {
            const int px1 = tid & 15, py1 = tid >> 4;
            float a0 = 0.f, a1 = 0.f, a2 = 0.f;
            #pragma unroll 4
            for (int ic = 0; ic < 64; ic++) {
                const float* sin = s_in + ic * ICS_A + py1 * RS_A + px1;
                const float* sw  = s_w + ic * 9;
                a0 += sw[0]*sin[0]   + sw[3]*sin[RS_A]   + sw[6]*sin[2*RS_A];
                a1 += sw[1]*sin[1]   + sw[4]*sin[RS_A+1] + sw[7]*sin[2*RS_A+1];
                a2 += sw[2]*sin[2]   + sw[5]*sin[RS_A+2] + sw[8]*sin[2*RS_A+2];
            }
            int pix = (ty0 + py1) * Ww + (tx0 + px1);
            g_thr[b * HWp + pix] = sigmoidf_(((a0 + a1) + a2) + b_rz[128]);
        }
    }
}

// ---------------------------------------------------------------------------
// Kernel B (R12 verbatim, measured 60.3us): 16x8 tile, 512 blocks, 128 thr.
// ---------------------------------------------------------------------------
__global__ void __launch_bounds__(128)
kB(const float* __restrict__ xt, const float* __restrict__ w_f,
   const float* __restrict__ b_f, float* __restrict__ out, int t)
{
    extern __shared__ float smem[];
    float* s_in = smem;
    float* s_w  = smem + SM_IN_B;

    const int tid  = threadIdx.x;
    const int tile = blockIdx.x;
    const int grp  = blockIdx.y;        // 0..3
    const int b    = blockIdx.z;
    const int ty0  = (tile >> 2) * 8;
    const int tx0  = (tile & 3) * 16;

    const int oc_base = grp * 16;
    const int ocq = tid >> 5;
    const int pg  = tid & 31;
    const int py  = pg >> 2;
    const int xb  = (pg & 3) * 4;

    float acc[4][4];
    #pragma unroll
    for (int k = 0; k < 4; k++)
        #pragma unroll
        for (int p = 0; p < 4; p++) acc[k][p] = 0.0f;

    for (int idx = tid; idx < 64 * 180; idx += 128) {
        int ic  = idx / 180;
        int rem = idx - ic * 180;
        int r   = rem / 18;
        int cc  = rem - r * 18;
        int gy  = ty0 + r - 1;
        int gx  = tx0 + cc - 1;
        float v = 0.0f;
        if (gy >= 0 && gy < Hh && gx >= 0 && gx < Ww)
            v = g_gate_in[((b * Cc + ic) * Hh + gy) * Ww + gx];
        s_in[ic * ICS_B + r * RS_B + cc] = v;
    }

    for (int cc0 = 0; cc0 < 64; cc0 += 8) {
        __syncthreads();
        #pragma unroll 4
        for (int i = tid; i < 8 * 16 * 9; i += 128) {
            int icl = i / 144;
            int rem = i - icl * 144;
            int oc  = rem / 9;
            int tap = rem - oc * 9;
            s_w[icl * 192 + oc * 12 + tap] =
                w_f[(oc_base + oc) * 576 + (cc0 + icl) * 9 + tap];
        }
        __syncthreads();
        #pragma unroll
        for (int icl = 0; icl < 8; icl++) {
            const float* sin = s_in + (cc0 + icl) * ICS_B + py * RS_B + xb;
            float x[3][8];
            #pragma unroll
            for (int dy = 0; dy < 3; dy++) {
                float4 a  = *(const float4*)(sin + dy * RS_B);
                float4 b4 = *(const float4*)(sin + dy * RS_B + 4);
                x[dy][0]=a.x;  x[dy][1]=a.y;  x[dy][2]=a.z;  x[dy][3]=a.w;
                x[dy][4]=b4.x; x[dy][5]=b4.y; x[dy][6]=b4.z; x[dy][7]=b4.w;
            }
            const float* sw = s_w + icl * 192 + (ocq * 4) * 12;
            #pragma unroll
            for (int k = 0; k < 4; k++) {
                float4 w0 = *(const float4*)(sw + k * 12);
                float4 w1 = *(const float4*)(sw + k * 12 + 4);
                float  w8 = sw[k * 12 + 8];
                float wv[9] = {w0.x, w0.y, w0.z, w0.w, w1.x, w1.y, w1.z, w1.w, w8};
                #pragma unroll
                for (int dy = 0; dy < 3; dy++)
                    #pragma unroll
                    for (int dx = 0; dx < 3; dx++) {
                        float wt = wv[dy * 3 + dx];
                        #pragma unroll
                        for (int p = 0; p < 4; p++)
                            acc[k][p] += wt * x[dy][dx + p];
                    }
            }
        }
    }

    const size_t N = (size_t)Tn * Bn * Cc * HWp;
    const int gy   = ty0 + py;
    const int pix0 = gy * Ww + tx0 + xb;
    const float4 thr4 = *(const float4*)&g_thr[b * HWp + pix0];
    const float thrv[4] = {thr4.x, thr4.y, thr4.z, thr4.w};

    #pragma unroll
    for (int k = 0; k < 4; k++) {
        int oc = oc_base + ocq * 4 + k;
        float bias = b_f[oc];
        size_t sidx = (size_t)(b * Cc + oc) * HWp + pix0;
        float4 xi = *(const float4*)&xt[((((size_t)t * Bn + b) * 192) + 128 + oc) * HWp + pix0];
        float4 u4 = *(const float4*)&g_upd[sidx];
        float4 hp4 = *(const float4*)&g_h[sidx];

        const float xiv[4] = {xi.x, xi.y, xi.z, xi.w};
        const float uv[4]  = {u4.x, u4.y, u4.z, u4.w};
        const float hpv[4] = {hp4.x, hp4.y, hp4.z, hp4.w};

        float4 yv, ev4, nd4, hn4;
        float* yp  = &yv.x;  float* evp = &ev4.x;
        float* ndp = &nd4.x; float* hnp = &hn4.x;

        #pragma unroll
        for (int p = 0; p < 4; p++) {
            float f   = acc[k][p] + bias + xiv[p];
            float ig  = tanhf(f);
            float h   = (1.0f - uv[p]) * hpv[p] + uv[p] * ig;
            float d   = h - thrv[p];
            float evt = (d > 0.0f) ? 1.0f : 0.0f;
            yp[p]  = evt * h;
            evp[p] = evt;
            ndp[p] = (d < 0.0f) ? (thrv[p] - h) : 0.0f;
            hnp[p] = h - evt * thrv[p];
        }

        size_t o = (((size_t)t * Bn + b) * Cc + oc) * HWp + pix0;
        *(float4*)&out[o]         = yv;
        *(float4*)&out[N + o]     = ev4;
        *(float4*)&out[2 * N + o] = nd4;
        *(float4*)&g_prev_y[sidx] = yv;
        *(float4*)&g_h[sidx]      = hn4;
    }
}

extern "C" void kernel_launch(void* const* d_in, const int* in_sizes, int n_in,
                              void* d_out, int out_size)
{
    const float* xt   = (const float*)d_in[0];
    const float* w_rz = (const float*)d_in[1];
    const float* b_rz = (const float*)d_in[2];
    const float* w_f  = (const float*)d_in[3];
    const float* b_f  = (const float*)d_in[4];
    float* out = (float*)d_out;

    cudaFuncSetAttribute(kA, cudaFuncAttributeMaxDynamicSharedMemorySize, SMEM_A);
    cudaFuncSetAttribute(kB, cudaFuncAttributeMaxDynamicSharedMemorySize, SMEM_B);

    // t = 0: exact fused elementwise step
    k0<<<1024, 256>>>(xt, b_rz, b_f, out);

    dim3 gA(16, 4, Bn);
    dim3 gB(32, 4, Bn);
    for (int t = 1; t < Tn; t++) {
        kA<<<gA, 512, SMEM_A>>>(xt, w_rz, b_rz, t);
        kB<<<gB, 128, SMEM_B>>>(xt, w_f, b_f, out, t);
    }
}

// round 15
// speedup vs baseline: 1.1449x; 1.1449x over previous
#include <cuda_runtime.h>
#include <cstddef>

#define Tn 10
#define Bn 4
#define Cc 64
#define Hh 64
#define Ww 64
#define HWp 4096

// kA: 16x16 tile, 18-row halo, row stride 20
#define RS_A 20
#define ICS_A 360
#define SM_IN_A (64*ICS_A)
#define SW_A 2304
#define SMEM_A ((SM_IN_A + SW_A)*4)    // 101376 B

// kB: 16x8 tile, 10-row halo, row stride 20
#define RS_B 20
#define ICS_B 200
#define SM_IN_B (64*ICS_B)
#define SW_B 1536
#define SMEM_B ((SM_IN_B + SW_B)*4)    // 57344 B

__device__ float g_prev_y [Bn*Cc*HWp];
__device__ float g_h      [Bn*Cc*HWp];
__device__ float g_gate_in[Bn*Cc*HWp];
__device__ float g_upd    [Bn*Cc*HWp];
__device__ float g_thr    [Bn*HWp];

// MUFU-based fast transcendentals (fp32):
//   sigmoid: 1 MUFU.EX2-based __expf + MUFU.RCP division
//   tanh(x) = 2*sigmoid(2x) - 1
__device__ __forceinline__ float sigmoidf_(float x) {
    return __fdividef(1.0f, 1.0f + __expf(-x));
}
__device__ __forceinline__ float tanhf_(float x) {
    return __fdividef(2.0f, 1.0f + __expf(-2.0f * x)) - 1.0f;
}

// ---------------------------------------------------------------------------
// Kernel 0 (t=0 only): all state zero -> convs reduce to biases. Exact.
// ---------------------------------------------------------------------------
__global__ void __launch_bounds__(256)
k0(const float* __restrict__ xt, const float* __restrict__ b_rz,
   const float* __restrict__ b_f, float* __restrict__ out)
{
    const int i4  = blockIdx.x * 256 + threadIdx.x;
    const int idx = i4 * 4;
    const int b   = idx >> 18;
    const int c   = (idx >> 12) & 63;

    const float thr = sigmoidf_(b_rz[128]);
    const float bz  = b_rz[c];
    const float bf  = b_f[c];

    float4 xz = *(const float4*)&xt[((size_t)b * 192 + c) * HWp + (idx & 4095)];
    float4 xf = *(const float4*)&xt[((size_t)b * 192 + 128 + c) * HWp + (idx & 4095)];
    const float xzv[4] = {xz.x, xz.y, xz.z, xz.w};
    const float xfv[4] = {xf.x, xf.y, xf.z, xf.w};

    float4 yv, ev4, nd4, hn4;
    float* yp  = &yv.x;  float* evp = &ev4.x;
    float* ndp = &nd4.x; float* hnp = &hn4.x;

    #pragma unroll
    for (int p = 0; p < 4; p++) {
        float u   = sigmoidf_(bz + xzv[p]);
        float ig  = tanhf_(bf + xfv[p]);
        float h   = u * ig;
        float d   = h - thr;
        float evt = (d > 0.0f) ? 1.0f : 0.0f;
        yp[p]  = evt * h;
        evp[p] = evt;
        ndp[p] = (d < 0.0f) ? (thr - h) : 0.0f;
        hnp[p] = h - evt * thr;
    }

    const size_t N = (size_t)Tn * Bn * Cc * HWp;
    *(float4*)&out[idx]          = yv;
    *(float4*)&out[N + idx]      = ev4;
    *(float4*)&out[2 * N + idx]  = nd4;
    *(float4*)&g_prev_y[idx]     = yv;
    *(float4*)&g_h[idx]          = hn4;
}

// ---------------------------------------------------------------------------
// Kernel A (R12 structure): 16x16 tile, 256 threads, 8oc x 4row/thread;
// grid (16,5,4): grp 0..3 = 32 oc, grp 4 = threshold channel.
// ---------------------------------------------------------------------------
__global__ void __launch_bounds__(256, 2)
kA(const float* __restrict__ xt, const float* __restrict__ w_rz,
   const float* __restrict__ b_rz, int t)
{
    extern __shared__ float smem[];
    float* s_in = smem;
    float* s_w  = smem + SM_IN_A;

    const int tid  = threadIdx.x;
    const int tile = blockIdx.x;   // 0..15
    const int grp  = blockIdx.y;   // 0..4
    const int b    = blockIdx.z;
    const int ty0  = (tile >> 2) * 16;
    const int tx0  = (tile & 3) * 16;

    for (int idx = tid; idx < 64 * 324; idx += 256) {
        int ic  = idx / 324;
        int rem = idx - ic * 324;
        int r   = rem / 18;
        int cc  = rem - r * 18;
        int gy  = ty0 + r - 1;
        int gx  = tx0 + cc - 1;
        float v = 0.0f;
        if (gy >= 0 && gy < Hh && gx >= 0 && gx < Ww)
            v = g_prev_y[((b * Cc + ic) * Hh + gy) * Ww + gx];
        s_in[ic * ICS_A + r * RS_A + cc] = v;
    }

    if (grp < 4) {
        const int oc_base = grp * 32;
        float acc[8][4];
        #pragma unroll
        for (int k = 0; k < 8; k++)
            #pragma unroll
            for (int i = 0; i < 4; i++) acc[k][i] = 0.0f;

        const int pixg = tid & 63;
        const int ocq  = tid >> 6;           // 0..3
        const int px   = pixg & 15;
        const int pyb  = (pixg >> 4) << 2;   // 0,4,8,12

        for (int cc0 = 0; cc0 < 64; cc0 += 8) {
            __syncthreads();
            for (int i = tid; i < 2304; i += 256) {
                int ocl  = i / 72;
                int rest = i - ocl * 72;  // icl*9 + tap
                s_w[i] = w_rz[(oc_base + ocl) * 576 + cc0 * 9 + rest];
            }
            __syncthreads();
            #pragma unroll
            for (int icl = 0; icl < 8; icl++) {
                const float* sin = s_in + (cc0 + icl) * ICS_A;
                const float* sw  = s_w + ocq * 8 * 72 + icl * 9;
                #pragma unroll
                for (int dy = 0; dy < 3; dy++) {
                    #pragma unroll
                    for (int dx = 0; dx < 3; dx++) {
                        int tap = dy * 3 + dx;
                        float x0 = sin[(pyb + 0 + dy) * RS_A + px + dx];
                        float x1 = sin[(pyb + 1 + dy) * RS_A + px + dx];
                        float x2 = sin[(pyb + 2 + dy) * RS_A + px + dx];
                        float x3 = sin[(pyb + 3 + dy) * RS_A + px + dx];
                        #pragma unroll
                        for (int k = 0; k < 8; k++) {
                            float w = sw[k * 72 + tap];
                            acc[k][0] += w * x0;
                            acc[k][1] += w * x1;
                            acc[k][2] += w * x2;
                            acc[k][3] += w * x3;
                        }
                    }
                }
            }
        }

        #pragma unroll
        for (int k = 0; k < 8; k++) {
            int oc = oc_base + ocq * 8 + k;
            float bias = b_rz[oc];
            #pragma unroll
            for (int i = 0; i < 4; i++) {
                int gy  = ty0 + pyb + i;
                int gx  = tx0 + px;
                int pix = gy * Ww + gx;
                float xi = xt[((((size_t)t * Bn + b) * 192) + oc) * HWp + pix];
                float s  = sigmoidf_(acc[k][i] + bias + xi);
                if (oc < 64) {
                    g_upd[(b * Cc + oc) * HWp + pix] = s;
                } else {
                    int c = oc - 64;
                    float py = s_in[c * ICS_A + (pyb + i + 1) * RS_A + (px + 1)];
                    g_gate_in[(b * Cc + c) * HWp + pix] = py * s;
                }
            }
        }
    } else {
        // Threshold channel (oc 128): 1 px/thread over 16x16
        for (int i = tid; i < 576; i += 256)
            s_w[i] = w_rz[128 * 576 + i];
        __syncthreads();
        float acc = 0.0f;
        const int px = tid & 15;
        const int py = tid >> 4;
        for (int ic = 0; ic < 64; ic++) {
            const float* sin = s_in + ic * ICS_A;
            const float* sw  = s_w + ic * 9;
            #pragma unroll
            for (int dy = 0; dy < 3; dy++)
                #pragma unroll
                for (int dx = 0; dx < 3; dx++)
                    acc += sw[dy * 3 + dx] * sin[(py + dy) * RS_A + px + dx];
        }
        int pix = (ty0 + py) * Ww + (tx0 + px);
        g_thr[b * HWp + pix] = sigmoidf_(acc + b_rz[128]);
    }
}

// ---------------------------------------------------------------------------
// Kernel B (R12 structure, measured 60.3us): 16x8 tile, 512 blocks, 128 thr.
// ---------------------------------------------------------------------------
__global__ void __launch_bounds__(128)
kB(const float* __restrict__ xt, const float* __restrict__ w_f,
   const float* __restrict__ b_f, float* __restrict__ out, int t)
{
    extern __shared__ float smem[];
    float* s_in = smem;
    float* s_w  = smem + SM_IN_B;

    const int tid  = threadIdx.x;
    const int tile = blockIdx.x;
    const int grp  = blockIdx.y;        // 0..3
    const int b    = blockIdx.z;
    const int ty0  = (tile >> 2) * 8;
    const int tx0  = (tile & 3) * 16;

    const int oc_base = grp * 16;
    const int ocq = tid >> 5;
    const int pg  = tid & 31;
    const int py  = pg >> 2;
    const int xb  = (pg & 3) * 4;

    float acc[4][4];
    #pragma unroll
    for (int k = 0; k < 4; k++)
        #pragma unroll
        for (int p = 0; p < 4; p++) acc[k][p] = 0.0f;

    for (int idx = tid; idx < 64 * 180; idx += 128) {
        int ic  = idx / 180;
        int rem = idx - ic * 180;
        int r   = rem / 18;
        int cc  = rem - r * 18;
        int gy  = ty0 + r - 1;
        int gx  = tx0 + cc - 1;
        float v = 0.0f;
        if (gy >= 0 && gy < Hh && gx >= 0 && gx < Ww)
            v = g_gate_in[((b * Cc + ic) * Hh + gy) * Ww + gx];
        s_in[ic * ICS_B + r * RS_B + cc] = v;
    }

    for (int cc0 = 0; cc0 < 64; cc0 += 8) {
        __syncthreads();
        #pragma unroll 4
        for (int i = tid; i < 8 * 16 * 9; i += 128) {
            int icl = i / 144;
            int rem = i - icl * 144;
            int oc  = rem / 9;
            int tap = rem - oc * 9;
            s_w[icl * 192 + oc * 12 + tap] =
                w_f[(oc_base + oc) * 576 + (cc0 + icl) * 9 + tap];
        }
        __syncthreads();
        #pragma unroll
        for (int icl = 0; icl < 8; icl++) {
            const float* sin = s_in + (cc0 + icl) * ICS_B + py * RS_B + xb;
            float x[3][8];
            #pragma unroll
            for (int dy = 0; dy < 3; dy++) {
                float4 a  = *(const float4*)(sin + dy * RS_B);
                float4 b4 = *(const float4*)(sin + dy * RS_B + 4);
                x[dy][0]=a.x;  x[dy][1]=a.y;  x[dy][2]=a.z;  x[dy][3]=a.w;
                x[dy][4]=b4.x; x[dy][5]=b4.y; x[dy][6]=b4.z; x[dy][7]=b4.w;
            }
            const float* sw = s_w + icl * 192 + (ocq * 4) * 12;
            #pragma unroll
            for (int k = 0; k < 4; k++) {
                float4 w0 = *(const float4*)(sw + k * 12);
                float4 w1 = *(const float4*)(sw + k * 12 + 4);
                float  w8 = sw[k * 12 + 8];
                float wv[9] = {w0.x, w0.y, w0.z, w0.w, w1.x, w1.y, w1.z, w1.w, w8};
                #pragma unroll
                for (int dy = 0; dy < 3; dy++)
                    #pragma unroll
                    for (int dx = 0; dx < 3; dx++) {
                        float wt = wv[dy * 3 + dx];
                        #pragma unroll
                        for (int p = 0; p < 4; p++)
                            acc[k][p] += wt * x[dy][dx + p];
                    }
            }
        }
    }

    const size_t N = (size_t)Tn * Bn * Cc * HWp;
    const int gy   = ty0 + py;
    const int pix0 = gy * Ww + tx0 + xb;
    const float4 thr4 = *(const float4*)&g_thr[b * HWp + pix0];
    const float thrv[4] = {thr4.x, thr4.y, thr4.z, thr4.w};

    #pragma unroll
    for (int k = 0; k < 4; k++) {
        int oc = oc_base + ocq * 4 + k;
        float bias = b_f[oc];
        size_t sidx = (size_t)(b * Cc + oc) * HWp + pix0;
        float4 xi = *(const float4*)&xt[((((size_t)t * Bn + b) * 192) + 128 + oc) * HWp + pix0];
        float4 u4 = *(const float4*)&g_upd[sidx];
        float4 hp4 = *(const float4*)&g_h[sidx];

        const float xiv[4] = {xi.x, xi.y, xi.z, xi.w};
        const float uv[4]  = {u4.x, u4.y, u4.z, u4.w};
        const float hpv[4] = {hp4.x, hp4.y, hp4.z, hp4.w};

        float4 yv, ev4, nd4, hn4;
        float* yp  = &yv.x;  float* evp = &ev4.x;
        float* ndp = &nd4.x; float* hnp = &hn4.x;

        #pragma unroll
        for (int p = 0; p < 4; p++) {
            float f   = acc[k][p] + bias + xiv[p];
            float ig  = tanhf_(f);
            float h   = (1.0f - uv[p]) * hpv[p] + uv[p] * ig;
            float d   = h - thrv[p];
            float evt = (d > 0.0f) ? 1.0f : 0.0f;
            yp[p]  = evt * h;
            evp[p] = evt;
            ndp[p] = (d < 0.0f) ? (thrv[p] - h) : 0.0f;
            hnp[p] = h - evt * thrv[p];
        }

        size_t o = (((size_t)t * Bn + b) * Cc + oc) * HWp + pix0;
        *(float4*)&out[o]         = yv;
        *(float4*)&out[N + o]     = ev4;
        *(float4*)&out[2 * N + o] = nd4;
        *(float4*)&g_prev_y[sidx] = yv;
        *(float4*)&g_h[sidx]      = hn4;
    }
}

extern "C" void kernel_launch(void* const* d_in, const int* in_sizes, int n_in,
                              void* d_out, int out_size)
{
    const float* xt   = (const float*)d_in[0];
    const float* w_rz = (const float*)d_in[1];
    const float* b_rz = (const float*)d_in[2];
    const float* w_f  = (const float*)d_in[3];
    const float* b_f  = (const float*)d_in[4];
    float* out = (float*)d_out;

    cudaFuncSetAttribute(kA, cudaFuncAttributeMaxDynamicSharedMemorySize, SMEM_A);
    cudaFuncSetAttribute(kB, cudaFuncAttributeMaxDynamicSharedMemorySize, SMEM_B);

    // t = 0: exact fused elementwise step
    k0<<<1024, 256>>>(xt, b_rz, b_f, out);

    dim3 gA(16, 5, Bn);
    dim3 gB(32, 4, Bn);
    for (int t = 1; t < Tn; t++) {
        kA<<<gA, 256, SMEM_A>>>(xt, w_rz, b_rz, t);
        kB<<<gB, 128, SMEM_B>>>(xt, w_f, b_f, out, t);
    }
}